// round 7
// baseline (speedup 1.0000x reference)
#include <cuda_runtime.h>
#include <cuda_bf16.h>
#include <cstdint>

#define DHID   512
#define KC     512
#define BM     64
#define BK     64          // K elems per chunk = 128 bytes bf16
#define NCH    (DHID/BK)   // 8 chunks
#define NT     512         // 16 warps

#define A_STAGE (BM * 128)             // 8 KB
#define B_STAGE (KC * 128)             // 64 KB
#define DYN_SMEM (2*A_STAGE + 3*B_STAGE + 1024)   // 16KB + 192KB + slack

__device__ __nv_bfloat16 g_wbf[KC * DHID];   // centers bf16, [n][k] row-major
__device__ float         g_c2[KC];

// ---------------------------------------------------------------------------
__device__ __forceinline__ uint32_t smem_u32(const void* p) {
    uint32_t a;
    asm("{ .reg .u64 t; cvta.to.shared.u64 t, %1; cvt.u32.u64 %0, t; }" : "=r"(a) : "l"(p));
    return a;
}
__device__ __forceinline__ uint32_t pack_bf16(float lo, float hi) {
    uint32_t r;
    asm("cvt.rn.bf16x2.f32 %0, %1, %2;" : "=r"(r) : "f"(hi), "f"(lo));
    return r;
}

__device__ __forceinline__ void cp_async16(uint32_t dst, const void* src) {
    asm volatile("cp.async.cg.shared.global [%0], [%1], 16;\n" :: "r"(dst), "l"(src) : "memory");
}
#define CP_COMMIT() asm volatile("cp.async.commit_group;\n" ::: "memory")
#define CP_WAITN(n) asm volatile("cp.async.wait_group %0;\n" :: "n"(n) : "memory")

#define LDSM4(r, a) \
    asm volatile("ldmatrix.sync.aligned.m8n8.x4.shared.b16 {%0,%1,%2,%3}, [%4];" \
                 : "=r"((r)[0]), "=r"((r)[1]), "=r"((r)[2]), "=r"((r)[3]) : "r"(a))

#define MMA16816(d, a, b0, b1) \
    asm volatile("mma.sync.aligned.m16n8k16.row.col.f32.bf16.bf16.f32 " \
                 "{%0,%1,%2,%3}, {%4,%5,%6,%7}, {%8,%9}, {%0,%1,%2,%3};" \
                 : "+f"((d)[0]), "+f"((d)[1]), "+f"((d)[2]), "+f"((d)[3]) \
                 : "r"((a)[0]), "r"((a)[1]), "r"((a)[2]), "r"((a)[3]), \
                   "r"(b0), "r"(b1))

// ---------------------------------------------------------------------------
// Prep: centers fp32 -> bf16 + ||c||^2. One block per cluster row.
// ---------------------------------------------------------------------------
__global__ void prep_kernel(const float* __restrict__ centers) {
    const int c = blockIdx.x, t = threadIdx.x;       // 256 threads
    const float2* row = reinterpret_cast<const float2*>(centers + (size_t)c * DHID);
    float2 v = row[t];
    reinterpret_cast<uint32_t*>(g_wbf + (size_t)c * DHID)[t] = pack_bf16(v.x, v.y);
    float s = v.x * v.x + v.y * v.y;
    #pragma unroll
    for (int o = 16; o > 0; o >>= 1) s += __shfl_xor_sync(0xffffffffu, s, o);
    __shared__ float ws[8];
    if ((t & 31) == 0) ws[t >> 5] = s;
    __syncthreads();
    if (t == 0) {
        float tot = 0.f;
        #pragma unroll
        for (int i = 0; i < 8; i++) tot += ws[i];
        g_c2[c] = tot;
    }
}

// ---------------------------------------------------------------------------
// Main fused kernel: 64 rows x 512 clusters per CTA, 16 warps (64x32 per warp).
// ---------------------------------------------------------------------------
extern __shared__ char dynsmem[];

__global__ __launch_bounds__(NT, 1)
void qsoft_mma_kernel(const float* __restrict__ x, float* __restrict__ out) {
    __shared__ float xs_sm[BM];
    __shared__ float c2s[KC];
    __shared__ float rs_sm[BM][16];
    __shared__ float inv_sm[BM];

    const int tid  = threadIdx.x;
    const int wid  = tid >> 5;
    const int lane = tid & 31;
    const int rowBase = blockIdx.x * BM;

    const uint32_t sbase = (smem_u32(dynsmem) + 1023u) & ~1023u;
    const uint32_t Abuf[2] = { sbase, sbase + A_STAGE };
    const uint32_t Bbuf[3] = { sbase + 2*A_STAGE,
                               sbase + 2*A_STAGE +     B_STAGE,
                               sbase + 2*A_STAGE + 2 * B_STAGE };

    // ---- A-load mapping: row = tid/8, 8 floats at col (tid%8)*8 ----
    const int arow = tid >> 3;
    const int asub = tid & 7;
    const float4* a_src_base = reinterpret_cast<const float4*>(
        x + (size_t)(rowBase + arow) * DHID + asub * 8);
    // swizzled A store offset: bits[9:7] of off = arow&7 (constant)
    const uint32_t a_dst_off = (uint32_t)arow * 128u
                             + (((uint32_t)asub * 16u) ^ (((uint32_t)arow & 7u) << 4));

    // ---- B-load mapping: 16B chunk (tid%8) of cluster row tid/8 (+64/iter) ----
    const int bn0 = tid >> 3, bi = tid & 7;
    const char* b_src_base = reinterpret_cast<const char*>(g_wbf)
                           + (size_t)bn0 * 1024 + bi * 16;
    const uint32_t b_dst_off = (uint32_t)bn0 * 128u
                             + (((uint32_t)bi * 16u) ^ (((uint32_t)bn0 & 7u) << 4));

    // ---- ldmatrix addressing: swizzle term = (lane&7)<<4 per thread ----
    const uint32_t swz  = ((uint32_t)lane & 7u) << 4;
    const int a_r  = ((lane >> 3) & 1) * 8 + (lane & 7);
    const int a_kb = ((lane >> 4) & 1) * 16;
    const int b_r  = ((lane >> 4) & 1) * 8 + (lane & 7);
    const int b_kb = ((lane >> 3) & 1) * 16;
    uint32_t ksA[4], ksB[4];
    #pragma unroll
    for (int ks = 0; ks < 4; ks++) {
        ksA[ks] = ((uint32_t)(ks * 32 + a_kb)) ^ swz;
        ksB[ks] = ((uint32_t)(ks * 32 + b_kb)) ^ swz;
    }
    const uint32_t aoff = (uint32_t)a_r * 128u;
    const uint32_t boff = (uint32_t)(wid * 32 + b_r) * 128u;

    float acc[4][4][4];
    #pragma unroll
    for (int mi = 0; mi < 4; mi++)
        #pragma unroll
        for (int ni = 0; ni < 4; ni++)
            #pragma unroll
            for (int e = 0; e < 4; e++) acc[mi][ni][e] = 0.f;

    float sq = 0.f;
    float4 f[2];

    // ---------------- loaders ----------------
    auto lda = [&](int c) {
        const float4* src = a_src_base + c * 16;   // 64 floats = 16 float4
        f[0] = src[0];
        f[1] = src[1];
    };
    auto sta = [&](int s) {
        sq += f[0].x*f[0].x + f[0].y*f[0].y + f[0].z*f[0].z + f[0].w*f[0].w;
        sq += f[1].x*f[1].x + f[1].y*f[1].y + f[1].z*f[1].z + f[1].w*f[1].w;
        uint32_t p0 = pack_bf16(f[0].x, f[0].y);
        uint32_t p1 = pack_bf16(f[0].z, f[0].w);
        uint32_t p2 = pack_bf16(f[1].x, f[1].y);
        uint32_t p3 = pack_bf16(f[1].z, f[1].w);
        asm volatile("st.shared.v4.b32 [%0], {%1,%2,%3,%4};"
                     :: "r"(Abuf[s] + a_dst_off),
                        "r"(p0), "r"(p1), "r"(p2), "r"(p3) : "memory");
    };
    auto ldb = [&](int c, int s) {
        const char* src = b_src_base + c * 128;
        uint32_t dst = Bbuf[s] + b_dst_off;
        #pragma unroll
        for (int k = 0; k < 8; k++) {
            cp_async16(dst, src);
            dst += 8192;           // +64 cluster rows
            src += 65536;
        }
    };

    // ---------------- compute one K-chunk (warp: 64 rows x 32 cols) ----------
    auto compute = [&](int as, int bs) {
        const uint32_t Ab = Abuf[as], Bb = Bbuf[bs];
        #pragma unroll
        for (int ks = 0; ks < 4; ks++) {
            const uint32_t tB = Bb + boff + ksB[ks];
            const uint32_t tA = Ab + aoff + ksA[ks];
            uint32_t b[2][4];
            LDSM4(b[0], tB);
            LDSM4(b[1], tB + 2048);
            #pragma unroll
            for (int mi = 0; mi < 4; mi++) {
                uint32_t a[4];
                LDSM4(a, tA + mi * 2048);
                MMA16816(acc[mi][0], a, b[0][0], b[0][1]);
                MMA16816(acc[mi][1], a, b[0][2], b[0][3]);
                MMA16816(acc[mi][2], a, b[1][0], b[1][1]);
                MMA16816(acc[mi][3], a, b[1][2], b[1][3]);
            }
        }
    };

    // ---------------- pipeline (3-stage B, 2-stage A) ----------------
    lda(0);
    ldb(0, 0); CP_COMMIT();
    ldb(1, 1); CP_COMMIT();
    sta(0);
    CP_WAITN(1);                       // chunk 0 landed
    __syncthreads();

    for (int c = 0; c < NCH; c++) {
        if (c + 2 < NCH) { ldb(c + 2, (c + 2) % 3); CP_COMMIT(); }
        if (c + 1 < NCH) lda(c + 1);
        compute(c & 1, c % 3);
        if (c + 1 < NCH) {
            sta((c + 1) & 1);
            if (c + 2 < NCH) CP_WAITN(1);   // chunk c+1 landed, c+2 may fly
            else             CP_WAITN(0);
        }
        __syncthreads();
    }

    // ---------------- epilogue ----------------
    sq += __shfl_xor_sync(0xffffffffu, sq, 1);
    sq += __shfl_xor_sync(0xffffffffu, sq, 2);
    sq += __shfl_xor_sync(0xffffffffu, sq, 4);
    if ((tid & 7) == 0) xs_sm[arow] = sq;
    for (int i = tid; i < KC; i += NT) c2s[i] = g_c2[i];
    __syncthreads();

    const int qrow = lane >> 2;            // 0..7
    const int wcol = wid * 32 + (lane & 3) * 2;

    float rsum[8];
    #pragma unroll
    for (int i = 0; i < 8; i++) rsum[i] = 0.f;

    #pragma unroll
    for (int mi = 0; mi < 4; mi++) {
        const float x20 = xs_sm[mi * 16 + qrow];
        const float x21 = xs_sm[mi * 16 + qrow + 8];
        #pragma unroll
        for (int ni = 0; ni < 4; ni++) {
            const float cc0 = c2s[wcol + ni * 8];
            const float cc1 = c2s[wcol + ni * 8 + 1];
            float q0 = __fdividef(1.f, 1.f + fmaxf(fmaf(-2.f, acc[mi][ni][0], x20 + cc0), 0.f));
            float q1 = __fdividef(1.f, 1.f + fmaxf(fmaf(-2.f, acc[mi][ni][1], x20 + cc1), 0.f));
            float q2 = __fdividef(1.f, 1.f + fmaxf(fmaf(-2.f, acc[mi][ni][2], x21 + cc0), 0.f));
            float q3 = __fdividef(1.f, 1.f + fmaxf(fmaf(-2.f, acc[mi][ni][3], x21 + cc1), 0.f));
            acc[mi][ni][0] = q0; acc[mi][ni][1] = q1;
            acc[mi][ni][2] = q2; acc[mi][ni][3] = q3;
            rsum[2*mi]   += q0 + q1;
            rsum[2*mi+1] += q2 + q3;
        }
    }
    #pragma unroll
    for (int i = 0; i < 8; i++) {
        float v = rsum[i];
        v += __shfl_xor_sync(0xffffffffu, v, 1);
        v += __shfl_xor_sync(0xffffffffu, v, 2);
        rsum[i] = v;
    }
    if ((lane & 3) == 0) {
        #pragma unroll
        for (int mi = 0; mi < 4; mi++) {
            rs_sm[mi * 16 + qrow][wid]     = rsum[2*mi];
            rs_sm[mi * 16 + qrow + 8][wid] = rsum[2*mi+1];
        }
    }
    __syncthreads();
    if (tid < BM) {
        float t = 0.f;
        #pragma unroll
        for (int w = 0; w < 16; w++) t += rs_sm[tid][w];
        inv_sm[tid] = __fdividef(1.f, t);
    }
    __syncthreads();

    #pragma unroll
    for (int mi = 0; mi < 4; mi++) {
        const int r0 = mi * 16 + qrow, r1 = r0 + 8;
        const float inv0 = inv_sm[r0], inv1 = inv_sm[r1];
        float* o0 = out + (size_t)(rowBase + r0) * KC + wcol;
        float* o1 = out + (size_t)(rowBase + r1) * KC + wcol;
        #pragma unroll
        for (int ni = 0; ni < 4; ni++) {
            *reinterpret_cast<float2*>(o0 + ni * 8) =
                make_float2(acc[mi][ni][0] * inv0, acc[mi][ni][1] * inv0);
            *reinterpret_cast<float2*>(o1 + ni * 8) =
                make_float2(acc[mi][ni][2] * inv1, acc[mi][ni][3] * inv1);
        }
    }
}

// ---------------------------------------------------------------------------
extern "C" void kernel_launch(void* const* d_in, const int* in_sizes, int n_in,
                              void* d_out, int out_size) {
    const float* x       = (const float*)d_in[0];
    const float* centers = (const float*)d_in[1];
    float*       out     = (float*)d_out;
    const int N = in_sizes[0] / DHID;   // 131072

    cudaFuncSetAttribute(qsoft_mma_kernel,
                         cudaFuncAttributeMaxDynamicSharedMemorySize, DYN_SMEM);

    prep_kernel<<<KC, 256>>>(centers);
    qsoft_mma_kernel<<<N / BM, NT, DYN_SMEM>>>(x, out);
}

// round 9
// speedup vs baseline: 1.0146x; 1.0146x over previous
#include <cuda_runtime.h>
#include <cuda_bf16.h>
#include <cstdint>

#define DHID   512
#define KC     512
#define BM     64
#define BK     64          // K elems per chunk = 128 bytes bf16
#define NCH    (DHID/BK)   // 8 chunks
#define NT     512         // 16 warps

#define A_STAGE (BM * 128)             // 8 KB
#define B_STAGE (KC * 128)             // 64 KB
#define DYN_SMEM (2*(A_STAGE + B_STAGE) + 1024)   // 144 KB + slack

__device__ __nv_bfloat16 g_wbf[KC * DHID];   // centers bf16, [n][k] row-major
__device__ float         g_c2[KC];

// ---------------------------------------------------------------------------
__device__ __forceinline__ uint32_t smem_u32(const void* p) {
    uint32_t a;
    asm("{ .reg .u64 t; cvta.to.shared.u64 t, %1; cvt.u32.u64 %0, t; }" : "=r"(a) : "l"(p));
    return a;
}
__device__ __forceinline__ uint32_t pack_bf16(float lo, float hi) {
    uint32_t r;
    asm("cvt.rn.bf16x2.f32 %0, %1, %2;" : "=r"(r) : "f"(hi), "f"(lo));
    return r;
}

__device__ __forceinline__ void cp_async16(uint32_t dst, const void* src) {
    asm volatile("cp.async.cg.shared.global [%0], [%1], 16;\n" :: "r"(dst), "l"(src) : "memory");
}
#define CP_COMMIT() asm volatile("cp.async.commit_group;\n" ::: "memory")
#define CP_WAIT0()  asm volatile("cp.async.wait_group 0;\n" ::: "memory")

#define LDSM4(r, a) \
    asm volatile("ldmatrix.sync.aligned.m8n8.x4.shared.b16 {%0,%1,%2,%3}, [%4];" \
                 : "=r"((r)[0]), "=r"((r)[1]), "=r"((r)[2]), "=r"((r)[3]) : "r"(a))

#define MMA16816(d, a, b0, b1) \
    asm volatile("mma.sync.aligned.m16n8k16.row.col.f32.bf16.bf16.f32 " \
                 "{%0,%1,%2,%3}, {%4,%5,%6,%7}, {%8,%9}, {%0,%1,%2,%3};" \
                 : "+f"((d)[0]), "+f"((d)[1]), "+f"((d)[2]), "+f"((d)[3]) \
                 : "r"((a)[0]), "r"((a)[1]), "r"((a)[2]), "r"((a)[3]), \
                   "r"(b0), "r"(b1))

// ---------------------------------------------------------------------------
// Prep: centers fp32 -> bf16 + ||c||^2. One block per cluster row.
// ---------------------------------------------------------------------------
__global__ void prep_kernel(const float* __restrict__ centers) {
    const int c = blockIdx.x, t = threadIdx.x;       // 256 threads
    const float2* row = reinterpret_cast<const float2*>(centers + (size_t)c * DHID);
    float2 v = row[t];
    reinterpret_cast<uint32_t*>(g_wbf + (size_t)c * DHID)[t] = pack_bf16(v.x, v.y);
    float s = v.x * v.x + v.y * v.y;
    #pragma unroll
    for (int o = 16; o > 0; o >>= 1) s += __shfl_xor_sync(0xffffffffu, s, o);
    __shared__ float ws[8];
    if ((t & 31) == 0) ws[t >> 5] = s;
    __syncthreads();
    if (t == 0) {
        float tot = 0.f;
        #pragma unroll
        for (int i = 0; i < 8; i++) tot += ws[i];
        g_c2[c] = tot;
    }
}

// ---------------------------------------------------------------------------
// Main fused kernel: 64 rows x 512 clusters per CTA, 16 warps (64x32 per warp).
// ---------------------------------------------------------------------------
extern __shared__ char dynsmem[];

__global__ __launch_bounds__(NT, 1)
void qsoft_mma_kernel(const float* __restrict__ x, float* __restrict__ out) {
    __shared__ float xs_sm[BM];
    __shared__ float c2s[KC];
    __shared__ float rs_sm[BM][16];
    __shared__ float inv_sm[BM];

    const int tid  = threadIdx.x;
    const int wid  = tid >> 5;
    const int lane = tid & 31;
    const int rowBase = blockIdx.x * BM;

    const uint32_t sbase = (smem_u32(dynsmem) + 1023u) & ~1023u;
    const uint32_t Abuf[2] = { sbase,              sbase + A_STAGE };
    const uint32_t Bbuf[2] = { sbase + 2*A_STAGE,  sbase + 2*A_STAGE + B_STAGE };

    // ---- A-load mapping: row = tid/8, 8 floats at col (tid%8)*8 ----
    const int arow = tid >> 3;
    const int asub = tid & 7;
    const float4* a_src_base = reinterpret_cast<const float4*>(
        x + (size_t)(rowBase + arow) * DHID + asub * 8);
    // swizzled A store offset: bits[9:7] of off = arow&7 (constant per thread)
    const uint32_t a_dst_off = (uint32_t)arow * 128u
                             + (((uint32_t)asub * 16u) ^ (((uint32_t)arow & 7u) << 4));

    // ---- B-load mapping: 16B chunk (tid%8) of cluster row tid/8 (+64/iter) ----
    const int bn0 = tid >> 3, bi = tid & 7;
    const char* b_src_base = reinterpret_cast<const char*>(g_wbf)
                           + (size_t)bn0 * 1024 + bi * 16;
    const uint32_t b_dst_off = (uint32_t)bn0 * 128u
                             + (((uint32_t)bi * 16u) ^ (((uint32_t)bn0 & 7u) << 4));

    // ---- ldmatrix addressing: swizzle term = (lane&7)<<4 per thread ----
    const uint32_t swz  = ((uint32_t)lane & 7u) << 4;
    const int a_r  = ((lane >> 3) & 1) * 8 + (lane & 7);
    const int a_kb = ((lane >> 4) & 1) * 16;
    const int b_r  = ((lane >> 4) & 1) * 8 + (lane & 7);
    const int b_kb = ((lane >> 3) & 1) * 16;
    uint32_t ksA[4], ksB[4];
    #pragma unroll
    for (int ks = 0; ks < 4; ks++) {
        ksA[ks] = ((uint32_t)(ks * 32 + a_kb)) ^ swz;
        ksB[ks] = ((uint32_t)(ks * 32 + b_kb)) ^ swz;
    }
    const uint32_t aoff = (uint32_t)a_r * 128u;
    const uint32_t boff = (uint32_t)(wid * 32 + b_r) * 128u;

    float acc[4][4][4];
    #pragma unroll
    for (int mi = 0; mi < 4; mi++)
        #pragma unroll
        for (int ni = 0; ni < 4; ni++)
            #pragma unroll
            for (int e = 0; e < 4; e++) acc[mi][ni][e] = 0.f;

    float sq = 0.f;
    float4 f[2];

    // ---------------- loaders ----------------
    auto lda = [&](int c) {
        const float4* src = a_src_base + c * 16;   // 64 floats = 16 float4
        f[0] = src[0];
        f[1] = src[1];
    };
    auto sta = [&](int s) {
        sq += f[0].x*f[0].x + f[0].y*f[0].y + f[0].z*f[0].z + f[0].w*f[0].w;
        sq += f[1].x*f[1].x + f[1].y*f[1].y + f[1].z*f[1].z + f[1].w*f[1].w;
        uint32_t p0 = pack_bf16(f[0].x, f[0].y);
        uint32_t p1 = pack_bf16(f[0].z, f[0].w);
        uint32_t p2 = pack_bf16(f[1].x, f[1].y);
        uint32_t p3 = pack_bf16(f[1].z, f[1].w);
        asm volatile("st.shared.v4.b32 [%0], {%1,%2,%3,%4};"
                     :: "r"(Abuf[s] + a_dst_off),
                        "r"(p0), "r"(p1), "r"(p2), "r"(p3) : "memory");
    };
    auto ldb = [&](int c, int s) {
        const char* src = b_src_base + c * 128;
        uint32_t dst = Bbuf[s] + b_dst_off;
        #pragma unroll
        for (int k = 0; k < 8; k++) {
            cp_async16(dst, src);
            dst += 8192;           // +64 cluster rows
            src += 65536;
        }
    };

    // ---------------- compute one K-chunk (warp: 64 rows x 32 cols) ----------
    auto compute = [&](int s) {
        const uint32_t Ab = Abuf[s], Bb = Bbuf[s];
        #pragma unroll
        for (int ks = 0; ks < 4; ks++) {
            const uint32_t tB = Bb + boff + ksB[ks];
            const uint32_t tA = Ab + aoff + ksA[ks];
            uint32_t b[2][4];
            LDSM4(b[0], tB);
            LDSM4(b[1], tB + 2048);
            #pragma unroll
            for (int mi = 0; mi < 4; mi++) {
                uint32_t a[4];
                LDSM4(a, tA + mi * 2048);
                MMA16816(acc[mi][0], a, b[0][0], b[0][1]);
                MMA16816(acc[mi][1], a, b[0][2], b[0][3]);
                MMA16816(acc[mi][2], a, b[1][0], b[1][1]);
                MMA16816(acc[mi][3], a, b[1][2], b[1][3]);
            }
        }
    };

    // ---------------- pipeline (2-stage double buffer) ----------------
    lda(0);
    ldb(0, 0); CP_COMMIT();
    sta(0);
    CP_WAIT0(); __syncthreads();

    for (int c = 0; c < NCH; c++) {
        const int s = c & 1;
        if (c + 1 < NCH) { lda(c + 1); ldb(c + 1, s ^ 1); CP_COMMIT(); }
        compute(s);
        if (c + 1 < NCH) { sta(s ^ 1); CP_WAIT0(); }
        __syncthreads();
    }

    // ---------------- epilogue ----------------
    sq += __shfl_xor_sync(0xffffffffu, sq, 1);
    sq += __shfl_xor_sync(0xffffffffu, sq, 2);
    sq += __shfl_xor_sync(0xffffffffu, sq, 4);
    if ((tid & 7) == 0) xs_sm[arow] = sq;
    for (int i = tid; i < KC; i += NT) c2s[i] = g_c2[i];
    __syncthreads();

    const int qrow = lane >> 2;            // 0..7
    const int wcol = wid * 32 + (lane & 3) * 2;

    float rsum[8];
    #pragma unroll
    for (int i = 0; i < 8; i++) rsum[i] = 0.f;

    #pragma unroll
    for (int mi = 0; mi < 4; mi++) {
        const float x20 = xs_sm[mi * 16 + qrow];
        const float x21 = xs_sm[mi * 16 + qrow + 8];
        #pragma unroll
        for (int ni = 0; ni < 4; ni++) {
            const float cc0 = c2s[wcol + ni * 8];
            const float cc1 = c2s[wcol + ni * 8 + 1];
            float q0 = __fdividef(1.f, 1.f + fmaxf(fmaf(-2.f, acc[mi][ni][0], x20 + cc0), 0.f));
            float q1 = __fdividef(1.f, 1.f + fmaxf(fmaf(-2.f, acc[mi][ni][1], x20 + cc1), 0.f));
            float q2 = __fdividef(1.f, 1.f + fmaxf(fmaf(-2.f, acc[mi][ni][2], x21 + cc0), 0.f));
            float q3 = __fdividef(1.f, 1.f + fmaxf(fmaf(-2.f, acc[mi][ni][3], x21 + cc1), 0.f));
            acc[mi][ni][0] = q0; acc[mi][ni][1] = q1;
            acc[mi][ni][2] = q2; acc[mi][ni][3] = q3;
            rsum[2*mi]   += q0 + q1;
            rsum[2*mi+1] += q2 + q3;
        }
    }
    #pragma unroll
    for (int i = 0; i < 8; i++) {
        float v = rsum[i];
        v += __shfl_xor_sync(0xffffffffu, v, 1);
        v += __shfl_xor_sync(0xffffffffu, v, 2);
        rsum[i] = v;
    }
    if ((lane & 3) == 0) {
        #pragma unroll
        for (int mi = 0; mi < 4; mi++) {
            rs_sm[mi * 16 + qrow][wid]     = rsum[2*mi];
            rs_sm[mi * 16 + qrow + 8][wid] = rsum[2*mi+1];
        }
    }
    __syncthreads();
    if (tid < BM) {
        float t = 0.f;
        #pragma unroll
        for (int w = 0; w < 16; w++) t += rs_sm[tid][w];
        inv_sm[tid] = __fdividef(1.f, t);
    }
    __syncthreads();

    #pragma unroll
    for (int mi = 0; mi < 4; mi++) {
        const int r0 = mi * 16 + qrow, r1 = r0 + 8;
        const float inv0 = inv_sm[r0], inv1 = inv_sm[r1];
        float* o0 = out + (size_t)(rowBase + r0) * KC + wcol;
        float* o1 = out + (size_t)(rowBase + r1) * KC + wcol;
        #pragma unroll
        for (int ni = 0; ni < 4; ni++) {
            *reinterpret_cast<float2*>(o0 + ni * 8) =
                make_float2(acc[mi][ni][0] * inv0, acc[mi][ni][1] * inv0);
            *reinterpret_cast<float2*>(o1 + ni * 8) =
                make_float2(acc[mi][ni][2] * inv1, acc[mi][ni][3] * inv1);
        }
    }
}

// ---------------------------------------------------------------------------
extern "C" void kernel_launch(void* const* d_in, const int* in_sizes, int n_in,
                              void* d_out, int out_size) {
    const float* x       = (const float*)d_in[0];
    const float* centers = (const float*)d_in[1];
    float*       out     = (float*)d_out;
    const int N = in_sizes[0] / DHID;   // 131072

    cudaFuncSetAttribute(qsoft_mma_kernel,
                         cudaFuncAttributeMaxDynamicSharedMemorySize, DYN_SMEM);

    prep_kernel<<<KC, 256>>>(centers);
    qsoft_mma_kernel<<<N / BM, NT, DYN_SMEM>>>(x, out);
}

// round 10
// speedup vs baseline: 1.2580x; 1.2399x over previous
#include <cuda_runtime.h>
#include <cuda_bf16.h>
#include <cstdint>

#define DHID   512
#define KC     512
#define BM     64
#define BK     64          // K elems per chunk = 128 bytes bf16
#define NCH    (DHID/BK)   // 8 chunks
#define NT     512         // 16 warps
#define NROWS  131072

#define A_STAGE (BM * 128)             // 8 KB
#define B_STAGE (KC * 128)             // 64 KB
#define DYN_SMEM (2*(A_STAGE + B_STAGE) + 1024)   // 144 KB + slack

__device__ __nv_bfloat16 g_wbf[KC * DHID];     // centers bf16, [n][k] row-major
__device__ float         g_c2[KC];
__device__ __nv_bfloat16 g_xbf[(size_t)NROWS * DHID];  // x bf16 (128 MB static)
__device__ float         g_x2[NROWS];

// ---------------------------------------------------------------------------
__device__ __forceinline__ uint32_t smem_u32(const void* p) {
    uint32_t a;
    asm("{ .reg .u64 t; cvta.to.shared.u64 t, %1; cvt.u32.u64 %0, t; }" : "=r"(a) : "l"(p));
    return a;
}
__device__ __forceinline__ uint32_t pack_bf16(float lo, float hi) {
    uint32_t r;
    asm("cvt.rn.bf16x2.f32 %0, %1, %2;" : "=r"(r) : "f"(hi), "f"(lo));
    return r;
}
#define SWZ128(o) ((o) ^ (((o) >> 3) & 0x70))

__device__ __forceinline__ void cp_async16(uint32_t dst, const void* src) {
    asm volatile("cp.async.cg.shared.global [%0], [%1], 16;\n" :: "r"(dst), "l"(src) : "memory");
}
#define CP_COMMIT() asm volatile("cp.async.commit_group;\n" ::: "memory")
#define CP_WAIT0()  asm volatile("cp.async.wait_group 0;\n" ::: "memory")

#define LDSM4(r, a) \
    asm volatile("ldmatrix.sync.aligned.m8n8.x4.shared.b16 {%0,%1,%2,%3}, [%4];" \
                 : "=r"((r)[0]), "=r"((r)[1]), "=r"((r)[2]), "=r"((r)[3]) : "r"(a))

#define MMA16816(d, a, b0, b1) \
    asm volatile("mma.sync.aligned.m16n8k16.row.col.f32.bf16.bf16.f32 " \
                 "{%0,%1,%2,%3}, {%4,%5,%6,%7}, {%8,%9}, {%0,%1,%2,%3};" \
                 : "+f"((d)[0]), "+f"((d)[1]), "+f"((d)[2]), "+f"((d)[3]) \
                 : "r"((a)[0]), "r"((a)[1]), "r"((a)[2]), "r"((a)[3]), \
                   "r"(b0), "r"(b1))

// ---------------------------------------------------------------------------
// Prep W: centers fp32 -> bf16 + ||c||^2. One block per cluster row.
// ---------------------------------------------------------------------------
__global__ void prep_w_kernel(const float* __restrict__ centers) {
    const int c = blockIdx.x, t = threadIdx.x;       // 256 threads
    const float2* row = reinterpret_cast<const float2*>(centers + (size_t)c * DHID);
    float2 v = row[t];
    reinterpret_cast<uint32_t*>(g_wbf + (size_t)c * DHID)[t] = pack_bf16(v.x, v.y);
    float s = v.x * v.x + v.y * v.y;
    #pragma unroll
    for (int o = 16; o > 0; o >>= 1) s += __shfl_xor_sync(0xffffffffu, s, o);
    __shared__ float ws[8];
    if ((t & 31) == 0) ws[t >> 5] = s;
    __syncthreads();
    if (t == 0) {
        float tot = 0.f;
        #pragma unroll
        for (int i = 0; i < 8; i++) tot += ws[i];
        g_c2[c] = tot;
    }
}

// ---------------------------------------------------------------------------
// Prep X: x fp32 -> bf16 + ||x||^2. One warp per row; 8 rows per block.
// ---------------------------------------------------------------------------
__global__ __launch_bounds__(256, 4)
void prep_x_kernel(const float* __restrict__ x) {
    const int tid  = threadIdx.x;
    const int wid  = tid >> 5;
    const int lane = tid & 31;
    const int row  = blockIdx.x * 8 + wid;

    const float4* src = reinterpret_cast<const float4*>(
        x + (size_t)row * DHID + lane * 16);
    float4 f0 = src[0], f1 = src[1], f2 = src[2], f3 = src[3];

    float s = f0.x*f0.x + f0.y*f0.y + f0.z*f0.z + f0.w*f0.w
            + f1.x*f1.x + f1.y*f1.y + f1.z*f1.z + f1.w*f1.w
            + f2.x*f2.x + f2.y*f2.y + f2.z*f2.z + f2.w*f2.w
            + f3.x*f3.x + f3.y*f3.y + f3.z*f3.z + f3.w*f3.w;

    uint4 o0, o1;
    o0.x = pack_bf16(f0.x, f0.y); o0.y = pack_bf16(f0.z, f0.w);
    o0.z = pack_bf16(f1.x, f1.y); o0.w = pack_bf16(f1.z, f1.w);
    o1.x = pack_bf16(f2.x, f2.y); o1.y = pack_bf16(f2.z, f2.w);
    o1.z = pack_bf16(f3.x, f3.y); o1.w = pack_bf16(f3.z, f3.w);

    uint4* dst = reinterpret_cast<uint4*>(g_xbf + (size_t)row * DHID + lane * 16);
    dst[0] = o0;
    dst[1] = o1;

    #pragma unroll
    for (int o = 16; o > 0; o >>= 1) s += __shfl_xor_sync(0xffffffffu, s, o);
    if (lane == 0) g_x2[row] = s;
}

// ---------------------------------------------------------------------------
// Main fused kernel: 64 rows x 512 clusters per CTA, 16 warps (64x32 per warp).
// ---------------------------------------------------------------------------
extern __shared__ char dynsmem[];

__global__ __launch_bounds__(NT, 1)
void qsoft_mma_kernel(float* __restrict__ out) {
    __shared__ float xs_sm[BM];
    __shared__ float c2s[KC];
    __shared__ float rs_sm[BM][16];
    __shared__ float inv_sm[BM];

    const int tid  = threadIdx.x;
    const int wid  = tid >> 5;
    const int lane = tid & 31;
    const int rowBase = blockIdx.x * BM;

    const uint32_t sbase = (smem_u32(dynsmem) + 1023u) & ~1023u;
    const uint32_t Abuf[2] = { sbase,              sbase + A_STAGE };
    const uint32_t Bbuf[2] = { sbase + 2*A_STAGE,  sbase + 2*A_STAGE + B_STAGE };

    // ldmatrix lane addressing (within-tile offsets)
    const int a_r  = ((lane >> 3) & 1) * 8 + (lane & 7);   // A row in m16
    const int a_kb = ((lane >> 4) & 1) * 16;               // A k-byte
    const int b_r  = ((lane >> 4) & 1) * 8 + (lane & 7);   // B row in n16
    const int b_kb = ((lane >> 3) & 1) * 16;               // B k-byte

    float acc[4][4][4];
    #pragma unroll
    for (int mi = 0; mi < 4; mi++)
        #pragma unroll
        for (int ni = 0; ni < 4; ni++)
            #pragma unroll
            for (int e = 0; e < 4; e++) acc[mi][ni][e] = 0.f;

    // ---------------- loaders (all cp.async) ----------------
    // A: 64 rows x 128B chunk = 512 x 16B, one per thread
    auto lda = [&](int c, int s) {
        int r = tid >> 3, i = tid & 7;
        const char* src = reinterpret_cast<const char*>(g_xbf)
                        + (size_t)(rowBase + r) * (DHID * 2) + c * 128 + i * 16;
        uint32_t off = (uint32_t)r * 128u + (uint32_t)i * 16u;
        cp_async16(Abuf[s] + SWZ128(off), src);
    };
    // B: 512 rows x 128B chunk = 4096 x 16B, 8 per thread
    auto ldb = [&](int c, int s) {
        #pragma unroll
        for (int k = 0; k < 8; k++) {
            int idx = tid + k * NT;
            int n = idx >> 3, i = idx & 7;
            const char* src = reinterpret_cast<const char*>(g_wbf)
                            + (size_t)n * (DHID * 2) + c * 128 + i * 16;
            uint32_t off = (uint32_t)n * 128u + (uint32_t)i * 16u;
            cp_async16(Bbuf[s] + SWZ128(off), src);
        }
    };

    // ---------------- compute one K-chunk (warp: 64 rows x 32 cols) ----------
    auto compute = [&](int s) {
        const uint32_t Ab = Abuf[s], Bb = Bbuf[s];
        #pragma unroll
        for (int ks = 0; ks < 4; ks++) {
            uint32_t b[2][4];
            #pragma unroll
            for (int j = 0; j < 2; j++) {
                uint32_t off = (uint32_t)(wid * 32 + j * 16 + b_r) * 128u
                             + (uint32_t)(ks * 32 + b_kb);
                LDSM4(b[j], Bb + SWZ128(off));
            }
            #pragma unroll
            for (int mi = 0; mi < 4; mi++) {
                uint32_t a[4];
                uint32_t off = (uint32_t)(mi * 16 + a_r) * 128u
                             + (uint32_t)(ks * 32 + a_kb);
                LDSM4(a, Ab + SWZ128(off));
                MMA16816(acc[mi][0], a, b[0][0], b[0][1]);
                MMA16816(acc[mi][1], a, b[0][2], b[0][3]);
                MMA16816(acc[mi][2], a, b[1][0], b[1][1]);
                MMA16816(acc[mi][3], a, b[1][2], b[1][3]);
            }
        }
    };

    // ---------------- pipeline (2-stage double buffer) ----------------
    lda(0, 0); ldb(0, 0); CP_COMMIT();
    CP_WAIT0(); __syncthreads();

    for (int c = 0; c < NCH; c++) {
        const int s = c & 1;
        if (c + 1 < NCH) { lda(c + 1, s ^ 1); ldb(c + 1, s ^ 1); CP_COMMIT(); }
        compute(s);
        if (c + 1 < NCH) CP_WAIT0();
        __syncthreads();
    }

    // ---------------- epilogue ----------------
    if (tid < BM) xs_sm[tid] = g_x2[rowBase + tid];
    for (int i = tid; i < KC; i += NT) c2s[i] = g_c2[i];
    __syncthreads();

    const int qrow = lane >> 2;            // 0..7
    const int wcol = wid * 32 + (lane & 3) * 2;

    float rsum[8];
    #pragma unroll
    for (int i = 0; i < 8; i++) rsum[i] = 0.f;

    #pragma unroll
    for (int mi = 0; mi < 4; mi++) {
        const float x20 = xs_sm[mi * 16 + qrow];
        const float x21 = xs_sm[mi * 16 + qrow + 8];
        #pragma unroll
        for (int ni = 0; ni < 4; ni++) {
            const float cc0 = c2s[wcol + ni * 8];
            const float cc1 = c2s[wcol + ni * 8 + 1];
            float q0 = __fdividef(1.f, 1.f + fmaxf(fmaf(-2.f, acc[mi][ni][0], x20 + cc0), 0.f));
            float q1 = __fdividef(1.f, 1.f + fmaxf(fmaf(-2.f, acc[mi][ni][1], x20 + cc1), 0.f));
            float q2 = __fdividef(1.f, 1.f + fmaxf(fmaf(-2.f, acc[mi][ni][2], x21 + cc0), 0.f));
            float q3 = __fdividef(1.f, 1.f + fmaxf(fmaf(-2.f, acc[mi][ni][3], x21 + cc1), 0.f));
            acc[mi][ni][0] = q0; acc[mi][ni][1] = q1;
            acc[mi][ni][2] = q2; acc[mi][ni][3] = q3;
            rsum[2*mi]   += q0 + q1;
            rsum[2*mi+1] += q2 + q3;
        }
    }
    #pragma unroll
    for (int i = 0; i < 8; i++) {
        float v = rsum[i];
        v += __shfl_xor_sync(0xffffffffu, v, 1);
        v += __shfl_xor_sync(0xffffffffu, v, 2);
        rsum[i] = v;
    }
    if ((lane & 3) == 0) {
        #pragma unroll
        for (int mi = 0; mi < 4; mi++) {
            rs_sm[mi * 16 + qrow][wid]     = rsum[2*mi];
            rs_sm[mi * 16 + qrow + 8][wid] = rsum[2*mi+1];
        }
    }
    __syncthreads();
    if (tid < BM) {
        float t = 0.f;
        #pragma unroll
        for (int w = 0; w < 16; w++) t += rs_sm[tid][w];
        inv_sm[tid] = __fdividef(1.f, t);
    }
    __syncthreads();

    #pragma unroll
    for (int mi = 0; mi < 4; mi++) {
        const int r0 = mi * 16 + qrow, r1 = r0 + 8;
        const float inv0 = inv_sm[r0], inv1 = inv_sm[r1];
        float* o0 = out + (size_t)(rowBase + r0) * KC + wcol;
        float* o1 = out + (size_t)(rowBase + r1) * KC + wcol;
        #pragma unroll
        for (int ni = 0; ni < 4; ni++) {
            *reinterpret_cast<float2*>(o0 + ni * 8) =
                make_float2(acc[mi][ni][0] * inv0, acc[mi][ni][1] * inv0);
            *reinterpret_cast<float2*>(o1 + ni * 8) =
                make_float2(acc[mi][ni][2] * inv1, acc[mi][ni][3] * inv1);
        }
    }
}

// ---------------------------------------------------------------------------
extern "C" void kernel_launch(void* const* d_in, const int* in_sizes, int n_in,
                              void* d_out, int out_size) {
    const float* x       = (const float*)d_in[0];
    const float* centers = (const float*)d_in[1];
    float*       out     = (float*)d_out;
    const int N = in_sizes[0] / DHID;   // 131072

    cudaFuncSetAttribute(qsoft_mma_kernel,
                         cudaFuncAttributeMaxDynamicSharedMemorySize, DYN_SMEM);

    prep_w_kernel<<<KC, 256>>>(centers);
    prep_x_kernel<<<N / 8, 256>>>(x);
    qsoft_mma_kernel<<<N / BM, NT, DYN_SMEM>>>(out);
}

// round 11
// speedup vs baseline: 1.2585x; 1.0004x over previous
#include <cuda_runtime.h>
#include <cuda_bf16.h>
#include <cstdint>

#define DHID   512
#define KC     512
#define BM     64
#define BK     64          // K elems per chunk = 128 bytes bf16
#define NCH    (DHID/BK)   // 8 chunks
#define NT     512         // 16 warps
#define NROWS  131072

#define A_STAGE (BM * 128)             // 8 KB
#define B_STAGE (KC * 128)             // 64 KB
#define DYN_SMEM (2*(A_STAGE + B_STAGE) + 1024)   // 144 KB + slack

__device__ __nv_bfloat16 g_wbf[KC * DHID];     // centers bf16, [n][k] row-major
__device__ float         g_c2[KC];
__device__ __nv_bfloat16 g_xbf[(size_t)NROWS * DHID];  // x bf16 (128 MB static)
__device__ float         g_x2[NROWS];

// ---------------------------------------------------------------------------
__device__ __forceinline__ uint32_t smem_u32(const void* p) {
    uint32_t a;
    asm("{ .reg .u64 t; cvta.to.shared.u64 t, %1; cvt.u32.u64 %0, t; }" : "=r"(a) : "l"(p));
    return a;
}
__device__ __forceinline__ uint32_t pack_bf16(float lo, float hi) {
    uint32_t r;
    asm("cvt.rn.bf16x2.f32 %0, %1, %2;" : "=r"(r) : "f"(hi), "f"(lo));
    return r;
}
#define SWZ128(o) ((o) ^ (((o) >> 3) & 0x70))

__device__ __forceinline__ void cp_async16(uint32_t dst, const void* src) {
    asm volatile("cp.async.cg.shared.global [%0], [%1], 16;\n" :: "r"(dst), "l"(src) : "memory");
}
#define CP_COMMIT() asm volatile("cp.async.commit_group;\n" ::: "memory")
#define CP_WAIT0()  asm volatile("cp.async.wait_group 0;\n" ::: "memory")

#define LDSM4(r, a) \
    asm volatile("ldmatrix.sync.aligned.m8n8.x4.shared.b16 {%0,%1,%2,%3}, [%4];" \
                 : "=r"((r)[0]), "=r"((r)[1]), "=r"((r)[2]), "=r"((r)[3]) : "r"(a))

#define MMA16816(d, a, b0, b1) \
    asm volatile("mma.sync.aligned.m16n8k16.row.col.f32.bf16.bf16.f32 " \
                 "{%0,%1,%2,%3}, {%4,%5,%6,%7}, {%8,%9}, {%0,%1,%2,%3};" \
                 : "+f"((d)[0]), "+f"((d)[1]), "+f"((d)[2]), "+f"((d)[3]) \
                 : "r"((a)[0]), "r"((a)[1]), "r"((a)[2]), "r"((a)[3]), \
                   "r"(b0), "r"(b1))

// ---------------------------------------------------------------------------
// Prep W: centers fp32 -> bf16 + ||c||^2. One block per cluster row.
// ---------------------------------------------------------------------------
__global__ void prep_w_kernel(const float* __restrict__ centers) {
    const int c = blockIdx.x, t = threadIdx.x;       // 256 threads
    const float2* row = reinterpret_cast<const float2*>(centers + (size_t)c * DHID);
    float2 v = row[t];
    reinterpret_cast<uint32_t*>(g_wbf + (size_t)c * DHID)[t] = pack_bf16(v.x, v.y);
    float s = v.x * v.x + v.y * v.y;
    #pragma unroll
    for (int o = 16; o > 0; o >>= 1) s += __shfl_xor_sync(0xffffffffu, s, o);
    __shared__ float ws[8];
    if ((t & 31) == 0) ws[t >> 5] = s;
    __syncthreads();
    if (t == 0) {
        float tot = 0.f;
        #pragma unroll
        for (int i = 0; i < 8; i++) tot += ws[i];
        g_c2[c] = tot;
    }
}

// ---------------------------------------------------------------------------
// Prep X: x fp32 -> bf16 + ||x||^2. One warp per row; 8 rows per block.
// ---------------------------------------------------------------------------
__global__ __launch_bounds__(256, 4)
void prep_x_kernel(const float* __restrict__ x) {
    const int tid  = threadIdx.x;
    const int wid  = tid >> 5;
    const int lane = tid & 31;
    const int row  = blockIdx.x * 8 + wid;

    const float4* src = reinterpret_cast<const float4*>(
        x + (size_t)row * DHID + lane * 16);
    float4 f0 = src[0], f1 = src[1], f2 = src[2], f3 = src[3];

    float s = f0.x*f0.x + f0.y*f0.y + f0.z*f0.z + f0.w*f0.w
            + f1.x*f1.x + f1.y*f1.y + f1.z*f1.z + f1.w*f1.w
            + f2.x*f2.x + f2.y*f2.y + f2.z*f2.z + f2.w*f2.w
            + f3.x*f3.x + f3.y*f3.y + f3.z*f3.z + f3.w*f3.w;

    uint4 o0, o1;
    o0.x = pack_bf16(f0.x, f0.y); o0.y = pack_bf16(f0.z, f0.w);
    o0.z = pack_bf16(f1.x, f1.y); o0.w = pack_bf16(f1.z, f1.w);
    o1.x = pack_bf16(f2.x, f2.y); o1.y = pack_bf16(f2.z, f2.w);
    o1.z = pack_bf16(f3.x, f3.y); o1.w = pack_bf16(f3.z, f3.w);

    uint4* dst = reinterpret_cast<uint4*>(g_xbf + (size_t)row * DHID + lane * 16);
    dst[0] = o0;
    dst[1] = o1;

    #pragma unroll
    for (int o = 16; o > 0; o >>= 1) s += __shfl_xor_sync(0xffffffffu, s, o);
    if (lane == 0) g_x2[row] = s;
}

// ---------------------------------------------------------------------------
// Main fused kernel: 64 rows x 512 clusters per CTA, 16 warps (64x32 per warp).
// ---------------------------------------------------------------------------
extern __shared__ char dynsmem[];

__global__ __launch_bounds__(NT, 1)
void qsoft_mma_kernel(float* __restrict__ out) {
    __shared__ float xs_sm[BM];
    __shared__ float c2s[KC];
    __shared__ float rs_sm[BM][16];
    __shared__ float inv_sm[BM];

    const int tid  = threadIdx.x;
    const int wid  = tid >> 5;
    const int lane = tid & 31;
    const int rowBase = blockIdx.x * BM;

    const uint32_t sbase = (smem_u32(dynsmem) + 1023u) & ~1023u;
    const uint32_t Abuf[2] = { sbase,              sbase + A_STAGE };
    const uint32_t Bbuf[2] = { sbase + 2*A_STAGE,  sbase + 2*A_STAGE + B_STAGE };

    // ldmatrix lane addressing (within-tile offsets)
    const int a_r  = ((lane >> 3) & 1) * 8 + (lane & 7);   // A row in m16
    const int a_kb = ((lane >> 4) & 1) * 16;               // A k-byte
    const int b_r  = ((lane >> 4) & 1) * 8 + (lane & 7);   // B row in n16
    const int b_kb = ((lane >> 3) & 1) * 16;               // B k-byte

    float acc[4][4][4];
    #pragma unroll
    for (int mi = 0; mi < 4; mi++)
        #pragma unroll
        for (int ni = 0; ni < 4; ni++)
            #pragma unroll
            for (int e = 0; e < 4; e++) acc[mi][ni][e] = 0.f;

    // ---------------- loaders (all cp.async) ----------------
    auto lda = [&](int c, int s) {
        int r = tid >> 3, i = tid & 7;
        const char* src = reinterpret_cast<const char*>(g_xbf)
                        + (size_t)(rowBase + r) * (DHID * 2) + c * 128 + i * 16;
        uint32_t off = (uint32_t)r * 128u + (uint32_t)i * 16u;
        cp_async16(Abuf[s] + SWZ128(off), src);
    };
    auto ldb = [&](int c, int s) {
        #pragma unroll
        for (int k = 0; k < 8; k++) {
            int idx = tid + k * NT;
            int n = idx >> 3, i = idx & 7;
            const char* src = reinterpret_cast<const char*>(g_wbf)
                            + (size_t)n * (DHID * 2) + c * 128 + i * 16;
            uint32_t off = (uint32_t)n * 128u + (uint32_t)i * 16u;
            cp_async16(Bbuf[s] + SWZ128(off), src);
        }
    };

    // ---------------- compute one K-chunk (warp: 64 rows x 32 cols) ----------
    // Batched LDSM: all 6 loads of a ks-step issue back-to-back (MLP=6),
    // then 16 MMAs run straight-line with no interior smem stalls.
    auto compute = [&](int s) {
        const uint32_t Ab = Abuf[s], Bb = Bbuf[s];
        #pragma unroll
        for (int ks = 0; ks < 4; ks++) {
            uint32_t b[2][4], a[4][4];
            #pragma unroll
            for (int j = 0; j < 2; j++) {
                uint32_t off = (uint32_t)(wid * 32 + j * 16 + b_r) * 128u
                             + (uint32_t)(ks * 32 + b_kb);
                LDSM4(b[j], Bb + SWZ128(off));
            }
            #pragma unroll
            for (int mi = 0; mi < 4; mi++) {
                uint32_t off = (uint32_t)(mi * 16 + a_r) * 128u
                             + (uint32_t)(ks * 32 + a_kb);
                LDSM4(a[mi], Ab + SWZ128(off));
            }
            #pragma unroll
            for (int mi = 0; mi < 4; mi++) {
                MMA16816(acc[mi][0], a[mi], b[0][0], b[0][1]);
                MMA16816(acc[mi][1], a[mi], b[0][2], b[0][3]);
                MMA16816(acc[mi][2], a[mi], b[1][0], b[1][1]);
                MMA16816(acc[mi][3], a[mi], b[1][2], b[1][3]);
            }
        }
    };

    // ---------------- pipeline (2-stage double buffer) ----------------
    lda(0, 0); ldb(0, 0); CP_COMMIT();
    CP_WAIT0(); __syncthreads();

    for (int c = 0; c < NCH; c++) {
        const int s = c & 1;
        if (c + 1 < NCH) { lda(c + 1, s ^ 1); ldb(c + 1, s ^ 1); CP_COMMIT(); }
        compute(s);
        if (c + 1 < NCH) CP_WAIT0();
        __syncthreads();
    }

    // ---------------- epilogue ----------------
    if (tid < BM) xs_sm[tid] = g_x2[rowBase + tid];
    for (int i = tid; i < KC; i += NT) c2s[i] = g_c2[i];
    __syncthreads();

    const int qrow = lane >> 2;            // 0..7
    const int wcol = wid * 32 + (lane & 3) * 2;

    float rsum[8];
    #pragma unroll
    for (int i = 0; i < 8; i++) rsum[i] = 0.f;

    #pragma unroll
    for (int mi = 0; mi < 4; mi++) {
        const float x20 = xs_sm[mi * 16 + qrow];
        const float x21 = xs_sm[mi * 16 + qrow + 8];
        #pragma unroll
        for (int ni = 0; ni < 4; ni++) {
            const float cc0 = c2s[wcol + ni * 8];
            const float cc1 = c2s[wcol + ni * 8 + 1];
            float q0 = __fdividef(1.f, 1.f + fmaxf(fmaf(-2.f, acc[mi][ni][0], x20 + cc0), 0.f));
            float q1 = __fdividef(1.f, 1.f + fmaxf(fmaf(-2.f, acc[mi][ni][1], x20 + cc1), 0.f));
            float q2 = __fdividef(1.f, 1.f + fmaxf(fmaf(-2.f, acc[mi][ni][2], x21 + cc0), 0.f));
            float q3 = __fdividef(1.f, 1.f + fmaxf(fmaf(-2.f, acc[mi][ni][3], x21 + cc1), 0.f));
            acc[mi][ni][0] = q0; acc[mi][ni][1] = q1;
            acc[mi][ni][2] = q2; acc[mi][ni][3] = q3;
            rsum[2*mi]   += q0 + q1;
            rsum[2*mi+1] += q2 + q3;
        }
    }
    #pragma unroll
    for (int i = 0; i < 8; i++) {
        float v = rsum[i];
        v += __shfl_xor_sync(0xffffffffu, v, 1);
        v += __shfl_xor_sync(0xffffffffu, v, 2);
        rsum[i] = v;
    }
    if ((lane & 3) == 0) {
        #pragma unroll
        for (int mi = 0; mi < 4; mi++) {
            rs_sm[mi * 16 + qrow][wid]     = rsum[2*mi];
            rs_sm[mi * 16 + qrow + 8][wid] = rsum[2*mi+1];
        }
    }
    __syncthreads();
    if (tid < BM) {
        float t = 0.f;
        #pragma unroll
        for (int w = 0; w < 16; w++) t += rs_sm[tid][w];
        inv_sm[tid] = __fdividef(1.f, t);
    }
    __syncthreads();

    #pragma unroll
    for (int mi = 0; mi < 4; mi++) {
        const int r0 = mi * 16 + qrow, r1 = r0 + 8;
        const float inv0 = inv_sm[r0], inv1 = inv_sm[r1];
        float* o0 = out + (size_t)(rowBase + r0) * KC + wcol;
        float* o1 = out + (size_t)(rowBase + r1) * KC + wcol;
        #pragma unroll
        for (int ni = 0; ni < 4; ni++) {
            *reinterpret_cast<float2*>(o0 + ni * 8) =
                make_float2(acc[mi][ni][0] * inv0, acc[mi][ni][1] * inv0);
            *reinterpret_cast<float2*>(o1 + ni * 8) =
                make_float2(acc[mi][ni][2] * inv1, acc[mi][ni][3] * inv1);
        }
    }
}

// ---------------------------------------------------------------------------
extern "C" void kernel_launch(void* const* d_in, const int* in_sizes, int n_in,
                              void* d_out, int out_size) {
    const float* x       = (const float*)d_in[0];
    const float* centers = (const float*)d_in[1];
    float*       out     = (float*)d_out;
    const int N = in_sizes[0] / DHID;   // 131072

    cudaFuncSetAttribute(qsoft_mma_kernel,
                         cudaFuncAttributeMaxDynamicSharedMemorySize, DYN_SMEM);

    prep_w_kernel<<<KC, 256>>>(centers);
    prep_x_kernel<<<N / 8, 256>>>(x);
    qsoft_mma_kernel<<<N / BM, NT, DYN_SMEM>>>(out);
}